// round 5
// baseline (speedup 1.0000x reference)
#include <cuda_runtime.h>

// out[b,p,:] = { c1*c2*c3, c0*c1, c0*c1*c2, c0*c1*c2*c3 }, c_i = cos(patches[b,p,i]).
// RZ params provably do not affect the output (unit phases cancel in |amp|^2).
//
// R5: 256-bit vector ld/st (sm_100+ v8.f32) -> 2 patches per thread with a
// single LDG.256 + STG.256; MUFU cosine for minimal instruction count.

#define TPB 256

__device__ __forceinline__ void qpatch8(const float x[8], float o[8]) {
    #pragma unroll
    for (int p = 0; p < 2; p++) {
        float c0 = __cosf(x[4 * p + 0]);
        float c1 = __cosf(x[4 * p + 1]);
        float c2 = __cosf(x[4 * p + 2]);
        float c3 = __cosf(x[4 * p + 3]);
        float c12  = c1 * c2;
        float c123 = c12 * c3;
        o[4 * p + 0] = c123;
        o[4 * p + 1] = c0 * c1;
        o[4 * p + 2] = c0 * c12;
        o[4 * p + 3] = c0 * c123;
    }
}

__global__ __launch_bounds__(TPB) void quantum_patch_kernel(
    const float* __restrict__ in,
    float* __restrict__ out) {
    size_t t = (size_t)blockIdx.x * TPB + threadIdx.x;
    const float* ip = in + t * 8;
    float* op = out + t * 8;

    float x[8];
    asm("ld.global.nc.v8.f32 {%0,%1,%2,%3,%4,%5,%6,%7}, [%8];"
        : "=f"(x[0]), "=f"(x[1]), "=f"(x[2]), "=f"(x[3]),
          "=f"(x[4]), "=f"(x[5]), "=f"(x[6]), "=f"(x[7])
        : "l"(ip));

    float o[8];
    qpatch8(x, o);

    asm volatile("st.global.v8.f32 [%0], {%1,%2,%3,%4,%5,%6,%7,%8};"
        :: "l"(op),
           "f"(o[0]), "f"(o[1]), "f"(o[2]), "f"(o[3]),
           "f"(o[4]), "f"(o[5]), "f"(o[6]), "f"(o[7])
        : "memory");
}

// Fallback (float4, guarded) for non-multiple sizes.
__global__ __launch_bounds__(TPB) void quantum_patch_kernel_guarded(
    const float4* __restrict__ in,
    float4* __restrict__ out,
    int n_patches) {
    int i = blockIdx.x * TPB + threadIdx.x;
    if (i < n_patches) {
        float4 x = in[i];
        float c0 = __cosf(x.x), c1 = __cosf(x.y), c2 = __cosf(x.z), c3 = __cosf(x.w);
        float c12 = c1 * c2;
        float c123 = c12 * c3;
        float4 o;
        o.x = c123;
        o.y = c0 * c1;
        o.z = c0 * c12;
        o.w = c0 * c123;
        out[i] = o;
    }
}

extern "C" void kernel_launch(void* const* d_in, const int* in_sizes, int n_in,
                              void* d_out, int out_size) {
    const float* patches = (const float*)d_in[0];     // (256, 2048, 4) f32
    float* out = (float*)d_out;                       // (256, 8192) f32 — same layout
    int n_patches = in_sizes[0] / 4;                  // 524288
    const int patches_per_block = TPB * 2;            // 512 (2 patches/thread)
    if (n_patches % patches_per_block == 0) {
        quantum_patch_kernel<<<n_patches / patches_per_block, TPB>>>(patches, out);  // 1024 CTAs
    } else {
        quantum_patch_kernel_guarded<<<(n_patches + TPB - 1) / TPB, TPB>>>(
            (const float4*)patches, (float4*)out, n_patches);
    }
}